// round 13
// baseline (speedup 1.0000x reference)
#include <cuda_runtime.h>
#include <cstdint>

#define NB    16
#define NPTS  65536
#define NSEED 40
#define RAD2  0.0025f

#define FPS_CL 8
#define FPS_T  1024
#define FPS_PT 8                 // NPTS / (FPS_CL * FPS_T)
#define FPS_PR (FPS_PT / 2)
#define NWARP  (FPS_T / 32)      // 32
#define EXW    (NWARP - 1)       // exchange warp = 31 (hi-wid arbiter priority)

__device__ float g_den[NB * NSEED];

// ---------------- f32x2 packed helpers (element-wise rn => bitwise == scalar)
__device__ __forceinline__ uint64_t pack2(float lo, float hi) {
    uint64_t r; asm("mov.b64 %0, {%1, %2};" : "=l"(r) : "f"(lo), "f"(hi)); return r;
}
__device__ __forceinline__ void unpack2(uint64_t v, float& lo, float& hi) {
    asm("mov.b64 {%0, %1}, %2;" : "=f"(lo), "=f"(hi) : "l"(v));
}
__device__ __forceinline__ uint64_t add2(uint64_t a, uint64_t b) {
    uint64_t r; asm("add.rn.f32x2 %0, %1, %2;" : "=l"(r) : "l"(a), "l"(b)); return r;
}
__device__ __forceinline__ uint64_t mul2(uint64_t a, uint64_t b) {
    uint64_t r; asm("mul.rn.f32x2 %0, %1, %2;" : "=l"(r) : "l"(a), "l"(b)); return r;
}
__device__ __forceinline__ uint64_t fma2(uint64_t a, uint64_t b, uint64_t c) {
    uint64_t r; asm("fma.rn.f32x2 %0, %1, %2, %3;" : "=l"(r) : "l"(a), "l"(b), "l"(c)); return r;
}

// ---------------- cluster / mbarrier helpers
__device__ __forceinline__ uint32_t ctarank() {
    uint32_t r; asm("mov.u32 %0, %%cluster_ctarank;" : "=r"(r)); return r;
}
__device__ __forceinline__ uint32_t mapa_u32(uint32_t sa, uint32_t rank) {
    uint32_t r; asm("mapa.shared::cluster.u32 %0, %1, %2;" : "=r"(r) : "r"(sa), "r"(rank));
    return r;
}
__device__ __forceinline__ void st_cluster_v4(uint32_t a, uint32_t x, uint32_t y,
                                              uint32_t z, uint32_t w) {
    asm volatile("st.shared::cluster.v4.b32 [%0], {%1,%2,%3,%4};"
                 :: "r"(a), "r"(x), "r"(y), "r"(z), "r"(w) : "memory");
}
__device__ __forceinline__ void st_cluster_b32(uint32_t a, uint32_t v) {
    asm volatile("st.shared::cluster.b32 [%0], %1;" :: "r"(a), "r"(v) : "memory");
}
__device__ __forceinline__ void mbar_init(uint32_t a, uint32_t cnt) {
    asm volatile("mbarrier.init.shared.b64 [%0], %1;" :: "r"(a), "r"(cnt) : "memory");
}
__device__ __forceinline__ void mbar_arrive_rel_cluster(uint32_t a) {
    asm volatile("mbarrier.arrive.release.cluster.shared::cluster.b64 _, [%0];"
                 :: "r"(a) : "memory");
}
__device__ __forceinline__ void mbar_wait_acq_cluster(uint32_t a, uint32_t parity) {
    asm volatile(
        "{\n\t.reg .pred P;\n\t"
        "WL_%=:\n\t"
        "mbarrier.try_wait.parity.acquire.cluster.shared::cta.b64 P, [%0], %1, 0x989680;\n\t"
        "@!P bra WL_%=;\n\t"
        "}" :: "r"(a), "r"(parity) : "memory");
}
__device__ __forceinline__ void cluster_sync_all() {
    asm volatile("barrier.cluster.arrive.aligned;" ::: "memory");
    asm volatile("barrier.cluster.wait.aligned;" ::: "memory");
}

// ---------------------------------------------------------------------------
// Kernel 1: FPS (R2-proven protocol, exchange on warp 31) + density HIDDEN
// inside each step's exchange window.
// 8-CTA cluster per batch, 1024 thr/CTA, 8 pts/thread register-resident
// packed f32x2 (element-wise rn => bitwise == reference scalar order).
// Per step: scan -> warp bfly max -> bar -> all-warp block max -> candidate
// atomicMin -> bar -> candidate publishes s_cand -> bar -> warp31 sends
// slots + arrives -> ALL warps compute density for seed k (overlapping the
// DSMEM flight / wait) -> warp31 waits once, reduces 8 slots, writes s_cent
// -> bar. After the loop: seed-39 density, 40 column sums, one atomicAdd per
// (CTA, seed). Tie-break: u64 key (distbits<<32)|~gi, max => first index ==
// jnp.argmax.
// ---------------------------------------------------------------------------
__global__ void __cluster_dims__(FPS_CL, 1, 1) __launch_bounds__(FPS_T, 1)
fps_kernel(const float* __restrict__ pcs)
{
    const uint32_t rank = ctarank();
    const int batch = blockIdx.x / FPS_CL;
    const int t = threadIdx.x;
    const int warp = t >> 5, lane = t & 31;

    __shared__ float s_warp[NWARP];
    __shared__ unsigned s_idx;
    __shared__ float s_cand[3];
    __shared__ float s_cent[3];
    __shared__ __align__(16) uint4 s_slot4[2][FPS_CL];   // {distbits, gi, xb, yb}
    __shared__ float s_slotz[2][FPS_CL];
    __shared__ __align__(8) unsigned long long s_mbar[2];
    __shared__ __align__(8) uint64_t s_npn[FPS_PR][FPS_T];   // -|p|^2 packed (32KB)
    __shared__ float s_wpart[NSEED][NWARP + 1];              // den partials

    const float* base = pcs + (size_t)batch * NPTS * 3;
    const int gi0 = (int)rank * (FPS_T * FPS_PT) + t;

    // ---- load points, pack pairs (2j, 2j+1)
    float lx[FPS_PT], ly[FPS_PT], lz[FPS_PT];
#pragma unroll
    for (int i = 0; i < FPS_PT; i++) {
        const int gi = gi0 + i * FPS_T;
        lx[i] = base[gi * 3 + 0];
        ly[i] = base[gi * 3 + 1];
        lz[i] = base[gi * 3 + 2];
    }
    uint64_t PX[FPS_PR], PY[FPS_PR], PZ[FPS_PR];
    float dist[FPS_PT];
#pragma unroll
    for (int j = 0; j < FPS_PR; j++) {
        PX[j] = pack2(lx[2 * j], lx[2 * j + 1]);
        PY[j] = pack2(ly[2 * j], ly[2 * j + 1]);
        PZ[j] = pack2(lz[2 * j], lz[2 * j + 1]);
    }
#pragma unroll
    for (int i = 0; i < FPS_PT; i++) dist[i] = 1e10f;

    // ---- precompute -|p|^2 per packed pair into smem (own slot only)
    const uint64_t signmask = 0x8000000080000000ull;
#pragma unroll
    for (int j = 0; j < FPS_PR; j++) {
        const uint64_t pn =
            add2(add2(mul2(PX[j], PX[j]), mul2(PY[j], PY[j])), mul2(PZ[j], PZ[j]));
        s_npn[j][t] = pn ^ signmask;
    }

    if (t == 0) {
        mbar_init((uint32_t)__cvta_generic_to_shared(&s_mbar[0]), FPS_CL);
        mbar_init((uint32_t)__cvta_generic_to_shared(&s_mbar[1]), FPS_CL);
        s_cent[0] = base[0]; s_cent[1] = base[1]; s_cent[2] = base[2];
    }
    if (rank == 0 && t < NSEED) g_den[batch * NSEED + t] = 0.0f;
    if (rank == 0 && t == 0) __threadfence();
    __syncthreads();
    cluster_sync_all();   // all mbarriers initialized cluster-wide

#pragma unroll 1
    for (int k = 0; k < NSEED - 1; k++) {
        const float cx = s_cent[0], cy = s_cent[1], cz = s_cent[2];
        const uint64_t ncx2 = pack2(-cx, -cx);
        const uint64_t ncy2 = pack2(-cy, -cy);
        const uint64_t ncz2 = pack2(-cz, -cz);

        // ---- packed scan: d = ((dx*dx + dy*dy) + dz*dz), exact rn order
        float bd = -1.0f;
#pragma unroll
        for (int j = 0; j < FPS_PR; j++) {
            const uint64_t dx2 = add2(PX[j], ncx2);
            const uint64_t dy2 = add2(PY[j], ncy2);
            const uint64_t dz2 = add2(PZ[j], ncz2);
            const uint64_t dd =
                add2(add2(mul2(dx2, dx2), mul2(dy2, dy2)), mul2(dz2, dz2));
            float d0, d1; unpack2(dd, d0, d1);
            dist[2 * j]     = fminf(dist[2 * j],     d0);
            dist[2 * j + 1] = fminf(dist[2 * j + 1], d1);
            bd = fmaxf(bd, dist[2 * j]);
            bd = fmaxf(bd, dist[2 * j + 1]);
        }

        // ---- warp bfly max
#pragma unroll
        for (int off = 16; off; off >>= 1)
            bd = fmaxf(bd, __shfl_xor_sync(0xffffffffu, bd, off));
        if (lane == 0) s_warp[warp] = bd;
        if (t == 0) s_idx = 0xffffffffu;
        __syncthreads();

        // ---- block max (every warp reduces the 32 warp maxima)
        float ctabd = s_warp[lane];
#pragma unroll
        for (int off = 16; off; off >>= 1)
            ctabd = fmaxf(ctabd, __shfl_xor_sync(0xffffffffu, ctabd, off));

        // ---- rare candidate warps: first index (min gi) via smem atomicMin
        if (bd == ctabd) {
            unsigned mygi = 0xffffffffu;
#pragma unroll
            for (int i = 0; i < FPS_PT; i++)
                if (dist[i] == ctabd) mygi = min(mygi, (unsigned)(gi0 + i * FPS_T));
            atomicMin(&s_idx, mygi);
        }
        __syncthreads();

        const unsigned widx = s_idx;
        if (bd == ctabd) {
#pragma unroll
            for (int i = 0; i < FPS_PT; i++) {
                if ((unsigned)(gi0 + i * FPS_T) == widx) {
                    float x0, x1, y0, y1, z0, z1;
                    unpack2(PX[i >> 1], x0, x1);
                    unpack2(PY[i >> 1], y0, y1);
                    unpack2(PZ[i >> 1], z0, z1);
                    s_cand[0] = (i & 1) ? x1 : x0;
                    s_cand[1] = (i & 1) ? y1 : y0;
                    s_cand[2] = (i & 1) ? z1 : z0;
                }
            }
        }
        __syncthreads();

        const int b = k & 1;

        // ---- warp31: launch the cluster exchange (sends + arrivals only)
        if (warp == EXW && lane < FPS_CL) {
            const unsigned dbts = __float_as_uint(ctabd);
            const unsigned xb = __float_as_uint(s_cand[0]);
            const unsigned yb = __float_as_uint(s_cand[1]);
            const unsigned zb = __float_as_uint(s_cand[2]);
            const uint32_t slot_loc =
                (uint32_t)__cvta_generic_to_shared(&s_slot4[b][rank]);
            const uint32_t zloc =
                (uint32_t)__cvta_generic_to_shared(&s_slotz[b][rank]);
            const uint32_t barloc =
                (uint32_t)__cvta_generic_to_shared(&s_mbar[b]);
            st_cluster_v4(mapa_u32(slot_loc, (uint32_t)lane), dbts, widx, xb, yb);
            st_cluster_b32(mapa_u32(zloc, (uint32_t)lane), zb);
            mbar_arrive_rel_cluster(mapa_u32(barloc, (uint32_t)lane));
        }

        // ---- ALL warps: density for seed k (hidden under DSMEM flight/wait)
        {
            const float qw = RAD2 - ((cx * cx + cy * cy) + cz * cz);
            const uint64_t qx2 = pack2(2.0f * cx, 2.0f * cx);
            const uint64_t qy2 = pack2(2.0f * cy, 2.0f * cy);
            const uint64_t qz2 = pack2(2.0f * cz, 2.0f * cz);
            const uint64_t qw2 = pack2(qw, qw);
            float acc = 0.0f;
#pragma unroll
            for (int j = 0; j < FPS_PR; j++) {
                uint64_t v = add2(qw2, s_npn[j][t]);
                v = fma2(PX[j], qx2, v);
                v = fma2(PY[j], qy2, v);
                v = fma2(PZ[j], qz2, v);
                float v0, v1; unpack2(v, v0, v1);
                acc += fmaxf(v0, 0.0f);
                acc += fmaxf(v1, 0.0f);
            }
#pragma unroll
            for (int off = 16; off; off >>= 1)
                acc += __shfl_xor_sync(0xffffffffu, acc, off);
            if (lane == 0) s_wpart[k][warp] = acc;
        }

        // ---- warp31: wait once, reduce the 8 slots, publish centroid
        if (warp == EXW) {
            mbar_wait_acq_cluster((uint32_t)__cvta_generic_to_shared(&s_mbar[b]),
                                  (unsigned)((k >> 1) & 1));

            const int l = lane & (FPS_CL - 1);
            const uint4 sl = s_slot4[b][l];
            const float slz = s_slotz[b][l];
            unsigned long long key =
                ((unsigned long long)sl.x << 32) | (unsigned)(~sl.y);
            const unsigned long long mykey = key;
#pragma unroll
            for (int off = 4; off; off >>= 1) {
                unsigned long long ok = __shfl_xor_sync(0xffffffffu, key, off);
                if (ok > key) key = ok;
            }
            const unsigned mask =
                __ballot_sync(0xffffffffu, mykey == key) & ((1u << FPS_CL) - 1u);
            const int src = __ffs(mask) - 1;
            const float wx = __shfl_sync(0xffffffffu, __uint_as_float(sl.z), src);
            const float wy = __shfl_sync(0xffffffffu, __uint_as_float(sl.w), src);
            const float wz = __shfl_sync(0xffffffffu, slz, src);
            if (lane == 0) { s_cent[0] = wx; s_cent[1] = wy; s_cent[2] = wz; }
        }
        __syncthreads();
    }

    // ---- density for the last seed (39)
    {
        const float cx = s_cent[0], cy = s_cent[1], cz = s_cent[2];
        const float qw = RAD2 - ((cx * cx + cy * cy) + cz * cz);
        const uint64_t qx2 = pack2(2.0f * cx, 2.0f * cx);
        const uint64_t qy2 = pack2(2.0f * cy, 2.0f * cy);
        const uint64_t qz2 = pack2(2.0f * cz, 2.0f * cz);
        const uint64_t qw2 = pack2(qw, qw);
        float acc = 0.0f;
#pragma unroll
        for (int j = 0; j < FPS_PR; j++) {
            uint64_t v = add2(qw2, s_npn[j][t]);
            v = fma2(PX[j], qx2, v);
            v = fma2(PY[j], qy2, v);
            v = fma2(PZ[j], qz2, v);
            float v0, v1; unpack2(v, v0, v1);
            acc += fmaxf(v0, 0.0f);
            acc += fmaxf(v1, 0.0f);
        }
#pragma unroll
        for (int off = 16; off; off >>= 1)
            acc += __shfl_xor_sync(0xffffffffu, acc, off);
        if (lane == 0) s_wpart[NSEED - 1][warp] = acc;
    }
    __syncthreads();

    // ---- 40 column sums, one atomicAdd per (CTA, seed)
    if (t < NSEED) {
        const float* row = &s_wpart[t][0];
        float a0 = 0.f, a1 = 0.f, a2 = 0.f, a3 = 0.f;
#pragma unroll
        for (int i = 0; i < NWARP; i += 4) {
            a0 += row[i]; a1 += row[i + 1]; a2 += row[i + 2]; a3 += row[i + 3];
        }
        atomicAdd(&g_den[batch * NSEED + t], (a0 + a1) + (a2 + a3));
    }
    cluster_sync_all();
}

// ---------------------------------------------------------------------------
// Kernel 2: out = mean_b( var_{ddof=1,s}( den[b][s] ) )
// ---------------------------------------------------------------------------
__global__ void var_kernel(float* __restrict__ out)
{
    const int lane = threadIdx.x;
    float v = 0.0f;
    if (lane < NB) {
        const float* d = &g_den[lane * NSEED];
        float s = 0.0f;
        for (int i = 0; i < NSEED; i++) s += d[i];
        const float m = s * (1.0f / NSEED);
        float q = 0.0f;
        for (int i = 0; i < NSEED; i++) {
            const float e = d[i] - m;
            q += e * e;
        }
        v = q * (1.0f / (NSEED - 1));
    }
#pragma unroll
    for (int off = 8; off; off >>= 1)
        v += __shfl_down_sync(0xffffffffu, v, off);
    if (lane == 0) out[0] = v * (1.0f / NB);
}

// ---------------------------------------------------------------------------
extern "C" void kernel_launch(void* const* d_in, const int* in_sizes, int n_in,
                              void* d_out, int out_size)
{
    const float* pcs = (const float*)d_in[0];
    (void)in_sizes; (void)n_in; (void)out_size;

    fps_kernel<<<NB * FPS_CL, FPS_T>>>(pcs);
    var_kernel<<<1, 32>>>((float*)d_out);
}

// round 14
// speedup vs baseline: 1.6423x; 1.6423x over previous
#include <cuda_runtime.h>
#include <cooperative_groups.h>
#include <cstdint>

namespace cg = cooperative_groups;

#define NB    16
#define NPTS  65536
#define NSEED 40
#define RAD2  0.0025f

#define FPS_CL 8
#define FPS_T  1024
#define FPS_PT 8                 // NPTS / (FPS_CL * FPS_T)
#define FPS_PR (FPS_PT / 2)

#define DEN_T      256
#define DEN_PT     8             // consecutive points per thread
#define DEN_PRR    (DEN_PT / 2)
#define DEN_CHUNKS (NPTS / (DEN_T * DEN_PT))   // 32

__device__ float g_seeds[NB * NSEED * 3];
__device__ float g_den[NB * NSEED];

// ---------------- f32x2 packed helpers (element-wise rn => bitwise == scalar)
__device__ __forceinline__ uint64_t pack2(float lo, float hi) {
    uint64_t r; asm("mov.b64 %0, {%1, %2};" : "=l"(r) : "f"(lo), "f"(hi)); return r;
}
__device__ __forceinline__ void unpack2(uint64_t v, float& lo, float& hi) {
    asm("mov.b64 {%0, %1}, %2;" : "=f"(lo), "=f"(hi) : "l"(v));
}
__device__ __forceinline__ uint64_t add2(uint64_t a, uint64_t b) {
    uint64_t r; asm("add.rn.f32x2 %0, %1, %2;" : "=l"(r) : "l"(a), "l"(b)); return r;
}
__device__ __forceinline__ uint64_t mul2(uint64_t a, uint64_t b) {
    uint64_t r; asm("mul.rn.f32x2 %0, %1, %2;" : "=l"(r) : "l"(a), "l"(b)); return r;
}
__device__ __forceinline__ uint64_t fma2(uint64_t a, uint64_t b, uint64_t c) {
    uint64_t r; asm("fma.rn.f32x2 %0, %1, %2, %3;" : "=l"(r) : "l"(a), "l"(b), "l"(c)); return r;
}

// ---------------- cluster / mbarrier helpers
__device__ __forceinline__ uint32_t ctarank() {
    uint32_t r; asm("mov.u32 %0, %%cluster_ctarank;" : "=r"(r)); return r;
}
__device__ __forceinline__ uint32_t mapa_u32(uint32_t sa, uint32_t rank) {
    uint32_t r; asm("mapa.shared::cluster.u32 %0, %1, %2;" : "=r"(r) : "r"(sa), "r"(rank));
    return r;
}
__device__ __forceinline__ void st_cluster_v4(uint32_t a, uint32_t x, uint32_t y,
                                              uint32_t z, uint32_t w) {
    asm volatile("st.shared::cluster.v4.b32 [%0], {%1,%2,%3,%4};"
                 :: "r"(a), "r"(x), "r"(y), "r"(z), "r"(w) : "memory");
}
__device__ __forceinline__ void st_cluster_b32(uint32_t a, uint32_t v) {
    asm volatile("st.shared::cluster.b32 [%0], %1;" :: "r"(a), "r"(v) : "memory");
}
__device__ __forceinline__ void mbar_init(uint32_t a, uint32_t cnt) {
    asm volatile("mbarrier.init.shared.b64 [%0], %1;" :: "r"(a), "r"(cnt) : "memory");
}
__device__ __forceinline__ void mbar_arrive_rel_cluster(uint32_t a) {
    asm volatile("mbarrier.arrive.release.cluster.shared::cluster.b64 _, [%0];"
                 :: "r"(a) : "memory");
}
__device__ __forceinline__ void mbar_wait_acq_cluster(uint32_t a, uint32_t parity) {
    asm volatile(
        "{\n\t.reg .pred P;\n\t"
        "WL_%=:\n\t"
        "mbarrier.try_wait.parity.acquire.cluster.shared::cta.b64 P, [%0], %1, 0x989680;\n\t"
        "@!P bra WL_%=;\n\t"
        "}" :: "r"(a), "r"(parity) : "memory");
}
__device__ __forceinline__ void cluster_sync_all() {
    asm volatile("barrier.cluster.arrive.aligned;" ::: "memory");
    asm volatile("barrier.cluster.wait.aligned;" ::: "memory");
}

// ---------------------------------------------------------------------------
// Kernel 1: farthest point sampling — the best-measured (R2/R10, 103-104us)
// protocol, verbatim. 8-CTA cluster per batch, 1024 thr/CTA, 8 pts/thread
// register-resident packed f32x2 (element-wise rn => bitwise == reference
// scalar order). Per step: packed scan -> warp bfly max -> block max (all
// warps) -> candidate atomicMin first-index -> candidate publishes xyz ->
// warp0 lanes 0..7 parallel DSMEM broadcast + mbar arrive -> warp0 waits
// once, reduces 8 slots, writes s_cent + g_seeds -> barrier.
// Tie-break: u64 key (distbits<<32)|~gi, max => first index == jnp.argmax.
// ---------------------------------------------------------------------------
__global__ void __cluster_dims__(FPS_CL, 1, 1) __launch_bounds__(FPS_T, 1)
fps_kernel(const float* __restrict__ pcs)
{
    const uint32_t rank = ctarank();
    const int batch = blockIdx.x / FPS_CL;
    const int t = threadIdx.x;
    const int warp = t >> 5, lane = t & 31;

    __shared__ float s_warp[32];
    __shared__ unsigned s_idx;
    __shared__ float s_cand[3];
    __shared__ float s_cent[3];
    __shared__ __align__(16) uint4 s_slot4[2][FPS_CL];   // {distbits, gi, xbits, ybits}
    __shared__ float s_slotz[2][FPS_CL];
    __shared__ __align__(8) unsigned long long s_mbar[2];

    const float* base = pcs + (size_t)batch * NPTS * 3;
    const int gi0 = (int)rank * (FPS_T * FPS_PT) + t;

    // load points, pack pairs (2j, 2j+1)
    float lx[FPS_PT], ly[FPS_PT], lz[FPS_PT];
#pragma unroll
    for (int i = 0; i < FPS_PT; i++) {
        const int gi = gi0 + i * FPS_T;
        lx[i] = base[gi * 3 + 0];
        ly[i] = base[gi * 3 + 1];
        lz[i] = base[gi * 3 + 2];
    }
    uint64_t PX[FPS_PR], PY[FPS_PR], PZ[FPS_PR];
    float dist[FPS_PT];
#pragma unroll
    for (int j = 0; j < FPS_PR; j++) {
        PX[j] = pack2(lx[2 * j], lx[2 * j + 1]);
        PY[j] = pack2(ly[2 * j], ly[2 * j + 1]);
        PZ[j] = pack2(lz[2 * j], lz[2 * j + 1]);
    }
#pragma unroll
    for (int i = 0; i < FPS_PT; i++) dist[i] = 1e10f;

    if (t == 0) {
        mbar_init((uint32_t)__cvta_generic_to_shared(&s_mbar[0]), FPS_CL);
        mbar_init((uint32_t)__cvta_generic_to_shared(&s_mbar[1]), FPS_CL);
        s_cent[0] = base[0]; s_cent[1] = base[1]; s_cent[2] = base[2];
    }
    if (rank == 0) {
        if (t < NSEED) g_den[batch * NSEED + t] = 0.0f;
        if (t == 0) {
            g_seeds[(batch * NSEED) * 3 + 0] = base[0];
            g_seeds[(batch * NSEED) * 3 + 1] = base[1];
            g_seeds[(batch * NSEED) * 3 + 2] = base[2];
        }
    }
    __syncthreads();
    cluster_sync_all();   // all mbarriers initialized cluster-wide

#pragma unroll 1
    for (int k = 0; k < NSEED - 1; k++) {
        const float cx = s_cent[0], cy = s_cent[1], cz = s_cent[2];
        const uint64_t ncx2 = pack2(-cx, -cx);
        const uint64_t ncy2 = pack2(-cy, -cy);
        const uint64_t ncz2 = pack2(-cz, -cz);

        // ---- packed scan: d = ((dx*dx + dy*dy) + dz*dz), exact rn order
        float bd = -1.0f;
#pragma unroll
        for (int j = 0; j < FPS_PR; j++) {
            const uint64_t dx2 = add2(PX[j], ncx2);
            const uint64_t dy2 = add2(PY[j], ncy2);
            const uint64_t dz2 = add2(PZ[j], ncz2);
            const uint64_t dd =
                add2(add2(mul2(dx2, dx2), mul2(dy2, dy2)), mul2(dz2, dz2));
            float d0, d1; unpack2(dd, d0, d1);
            dist[2 * j]     = fminf(dist[2 * j],     d0);
            dist[2 * j + 1] = fminf(dist[2 * j + 1], d1);
            bd = fmaxf(bd, dist[2 * j]);
            bd = fmaxf(bd, dist[2 * j + 1]);
        }

        // ---- warp bfly max
#pragma unroll
        for (int off = 16; off; off >>= 1)
            bd = fmaxf(bd, __shfl_xor_sync(0xffffffffu, bd, off));
        if (lane == 0) s_warp[warp] = bd;
        if (t == 0) s_idx = 0xffffffffu;
        __syncthreads();

        // ---- block max (every warp reduces the 32 warp maxima)
        float ctabd = s_warp[lane];
#pragma unroll
        for (int off = 16; off; off >>= 1)
            ctabd = fmaxf(ctabd, __shfl_xor_sync(0xffffffffu, ctabd, off));

        // ---- rare candidate warps: first index (min gi) via smem atomicMin
        if (bd == ctabd) {
            unsigned mygi = 0xffffffffu;
#pragma unroll
            for (int i = 0; i < FPS_PT; i++)
                if (dist[i] == ctabd) mygi = min(mygi, (unsigned)(gi0 + i * FPS_T));
            atomicMin(&s_idx, mygi);
        }
        __syncthreads();

        const unsigned widx = s_idx;
        if (bd == ctabd) {
#pragma unroll
            for (int i = 0; i < FPS_PT; i++) {
                if ((unsigned)(gi0 + i * FPS_T) == widx) {
                    float x0, x1, y0, y1, z0, z1;
                    unpack2(PX[i >> 1], x0, x1);
                    unpack2(PY[i >> 1], y0, y1);
                    unpack2(PZ[i >> 1], z0, z1);
                    s_cand[0] = (i & 1) ? x1 : x0;
                    s_cand[1] = (i & 1) ? y1 : y0;
                    s_cand[2] = (i & 1) ? z1 : z0;
                }
            }
        }
        __syncthreads();

        // ---- cross-CTA exchange (warp0 only), double-buffered slots+mbarrier
        const int b = k & 1;
        if (warp == 0) {
            if (lane < FPS_CL) {
                const unsigned db = __float_as_uint(ctabd);
                const unsigned xb = __float_as_uint(s_cand[0]);
                const unsigned yb = __float_as_uint(s_cand[1]);
                const unsigned zb = __float_as_uint(s_cand[2]);
                const uint32_t slot_loc =
                    (uint32_t)__cvta_generic_to_shared(&s_slot4[b][rank]);
                const uint32_t zloc =
                    (uint32_t)__cvta_generic_to_shared(&s_slotz[b][rank]);
                const uint32_t barloc =
                    (uint32_t)__cvta_generic_to_shared(&s_mbar[b]);
                const uint32_t slot_rem = mapa_u32(slot_loc, (uint32_t)lane);
                const uint32_t z_rem    = mapa_u32(zloc,    (uint32_t)lane);
                const uint32_t bar_rem  = mapa_u32(barloc,  (uint32_t)lane);
                st_cluster_v4(slot_rem, db, widx, xb, yb);
                st_cluster_b32(z_rem, zb);
                mbar_arrive_rel_cluster(bar_rem);
            }
            mbar_wait_acq_cluster((uint32_t)__cvta_generic_to_shared(&s_mbar[b]),
                                  (unsigned)((k >> 1) & 1));

            const int l = lane & (FPS_CL - 1);
            const uint4 sl = s_slot4[b][l];
            const float slz = s_slotz[b][l];
            unsigned long long key =
                ((unsigned long long)sl.x << 32) | (unsigned)(~sl.y);
            const unsigned long long mykey = key;
#pragma unroll
            for (int off = 4; off; off >>= 1) {
                unsigned long long ok = __shfl_xor_sync(0xffffffffu, key, off);
                if (ok > key) key = ok;
            }
            const unsigned mask =
                __ballot_sync(0xffffffffu, mykey == key) & ((1u << FPS_CL) - 1u);
            const int src = __ffs(mask) - 1;
            const float wx = __shfl_sync(0xffffffffu, __uint_as_float(sl.z), src);
            const float wy = __shfl_sync(0xffffffffu, __uint_as_float(sl.w), src);
            const float wz = __shfl_sync(0xffffffffu, slz, src);
            if (lane == 0) { s_cent[0] = wx; s_cent[1] = wy; s_cent[2] = wz; }
            if (rank == 0 && lane == 1) {
                float* gs = &g_seeds[(batch * NSEED + k + 1) * 3];
                gs[0] = wx; gs[1] = wy; gs[2] = wz;
            }
        }
        __syncthreads();
    }
    cluster_sync_all();
}

// ---------------------------------------------------------------------------
// Kernel 2: den[b][s] = sum_n relu(r^2 - (|s|^2 + |p|^2 - 2 s.p))
// Each thread: 8 CONSECUTIVE points via 6x LDG.128 (16B-aligned since
// p0*12B with p0 % 8 == 0), packed f32x2 pairs, 40-seed FMA sweep,
// sparse predicated atomicAdd.
// ---------------------------------------------------------------------------
__global__ void __launch_bounds__(DEN_T)
den_kernel(const float* __restrict__ pcs)
{
    const int batch = blockIdx.y;
    const int chunk = blockIdx.x;
    const int t = threadIdx.x;

    __shared__ float4 ss[NSEED];
    if (t < NSEED) {
        const float* gs = &g_seeds[(batch * NSEED + t) * 3];
        const float sx = gs[0], sy = gs[1], sz = gs[2];
        const float sn = sx * sx + sy * sy + sz * sz;
        ss[t] = make_float4(2.0f * sx, 2.0f * sy, 2.0f * sz, RAD2 - sn);
    }
    __syncthreads();

    const float* base = pcs + (size_t)batch * NPTS * 3;
    const int p0 = (chunk * DEN_T + t) * DEN_PT;     // 8 consecutive points

    // 6 x float4 = 24 floats = 8 points (vectorized, aligned)
    const float4* fp = reinterpret_cast<const float4*>(base + (size_t)p0 * 3);
    float f[DEN_PT * 3];
#pragma unroll
    for (int i = 0; i < (DEN_PT * 3) / 4; i++) {
        const float4 v = __ldg(&fp[i]);
        f[4 * i + 0] = v.x; f[4 * i + 1] = v.y;
        f[4 * i + 2] = v.z; f[4 * i + 3] = v.w;
    }

    uint64_t X2[DEN_PRR], Y2[DEN_PRR], Z2[DEN_PRR], NPN2[DEN_PRR];
#pragma unroll
    for (int j = 0; j < DEN_PRR; j++) {
        const float x0 = f[6 * j + 0], y0 = f[6 * j + 1], z0 = f[6 * j + 2];
        const float x1 = f[6 * j + 3], y1 = f[6 * j + 4], z1 = f[6 * j + 5];
        X2[j] = pack2(x0, x1);
        Y2[j] = pack2(y0, y1);
        Z2[j] = pack2(z0, z1);
        const float pn0 = fmaf(z0, z0, fmaf(y0, y0, x0 * x0));
        const float pn1 = fmaf(z1, z1, fmaf(y1, y1, x1 * x1));
        NPN2[j] = pack2(-pn0, -pn1);
    }

#pragma unroll 2
    for (int s = 0; s < NSEED; s++) {
        const float4 q = ss[s];
        const uint64_t qx2 = pack2(q.x, q.x);
        const uint64_t qy2 = pack2(q.y, q.y);
        const uint64_t qz2 = pack2(q.z, q.z);
        const uint64_t qw2 = pack2(q.w, q.w);
        float acc = 0.0f;
#pragma unroll
        for (int j = 0; j < DEN_PRR; j++) {
            uint64_t v = add2(qw2, NPN2[j]);
            v = fma2(X2[j], qx2, v);
            v = fma2(Y2[j], qy2, v);
            v = fma2(Z2[j], qz2, v);
            float v0, v1; unpack2(v, v0, v1);
            acc += fmaxf(v0, 0.0f);
            acc += fmaxf(v1, 0.0f);
        }
        if (acc != 0.0f) atomicAdd(&g_den[batch * NSEED + s], acc);
    }
}

// ---------------------------------------------------------------------------
// Kernel 3: out = mean_b( var_{ddof=1,s}( den[b][s] ) )
// ---------------------------------------------------------------------------
__global__ void var_kernel(float* __restrict__ out)
{
    const int lane = threadIdx.x;
    float v = 0.0f;
    if (lane < NB) {
        const float* d = &g_den[lane * NSEED];
        float s = 0.0f;
        for (int i = 0; i < NSEED; i++) s += d[i];
        const float m = s * (1.0f / NSEED);
        float q = 0.0f;
        for (int i = 0; i < NSEED; i++) {
            const float e = d[i] - m;
            q += e * e;
        }
        v = q * (1.0f / (NSEED - 1));
    }
#pragma unroll
    for (int off = 8; off; off >>= 1)
        v += __shfl_down_sync(0xffffffffu, v, off);
    if (lane == 0) out[0] = v * (1.0f / NB);
}

// ---------------------------------------------------------------------------
extern "C" void kernel_launch(void* const* d_in, const int* in_sizes, int n_in,
                              void* d_out, int out_size)
{
    const float* pcs = (const float*)d_in[0];
    (void)in_sizes; (void)n_in; (void)out_size;

    fps_kernel<<<NB * FPS_CL, FPS_T>>>(pcs);
    den_kernel<<<dim3(DEN_CHUNKS, NB), DEN_T>>>(pcs);
    var_kernel<<<1, 32>>>((float*)d_out);
}